// round 1
// baseline (speedup 1.0000x reference)
#include <cuda_runtime.h>
#include <cuda_bf16.h>
#include <math.h>

// ---------------- problem constants ----------------
#define S_    2048
#define D_    2048
#define HID_  5632
#define NH_   32
#define NKV_  8
#define HD_   64
#define KV_   (NKV_*HD_)   // 512

// ---------------- scratch (no allocation allowed) ----------------
__device__ float g_h [S_*D_];
__device__ float g_q [S_*D_];
__device__ float g_k [S_*KV_];
__device__ float g_v [S_*KV_];
__device__ float g_ao[S_*D_];
__device__ float g_x1[S_*D_];
__device__ float g_h2[S_*D_];
__device__ float g_p1[S_*HID_];
__device__ float g_p3[S_*HID_];

// ---------------- packed f32x2 helpers (full-rate fp32 on sm_103a) ----------------
__device__ __forceinline__ unsigned long long splat2(float a) {
    unsigned long long r;
    asm("mov.b64 %0, {%1, %1};" : "=l"(r) : "f"(a));
    return r;
}
__device__ __forceinline__ void fma2(unsigned long long &d, unsigned long long a, unsigned long long b) {
    asm("fma.rn.f32x2 %0, %1, %2, %0;" : "+l"(d) : "l"(a), "l"(b));
}
__device__ __forceinline__ float2 unpack2(unsigned long long v) {
    float2 r;
    asm("mov.b64 {%0, %1}, %2;" : "=f"(r.x), "=f"(r.y) : "l"(v));
    return r;
}

// ---------------- LayerNorm: one block per row, 256 threads ----------------
__global__ __launch_bounds__(256) void ln_kernel(const float* __restrict__ x,
                                                 const float* __restrict__ w,
                                                 const float* __restrict__ b,
                                                 float* __restrict__ out) {
    int row = blockIdx.x;
    const float4* xr = (const float4*)(x + (size_t)row * D_);
    float4 v0 = xr[threadIdx.x * 2 + 0];
    float4 v1 = xr[threadIdx.x * 2 + 1];
    float s  = v0.x + v0.y + v0.z + v0.w + v1.x + v1.y + v1.z + v1.w;
    float ss = v0.x*v0.x + v0.y*v0.y + v0.z*v0.z + v0.w*v0.w
             + v1.x*v1.x + v1.y*v1.y + v1.z*v1.z + v1.w*v1.w;
    #pragma unroll
    for (int o = 16; o; o >>= 1) {
        s  += __shfl_xor_sync(0xffffffffu, s,  o);
        ss += __shfl_xor_sync(0xffffffffu, ss, o);
    }
    __shared__ float sm[18];
    int warp = threadIdx.x >> 5, lane = threadIdx.x & 31;
    if (lane == 0) { sm[warp] = s; sm[8 + warp] = ss; }
    __syncthreads();
    if (threadIdx.x == 0) {
        float S1 = 0.f, S2 = 0.f;
        #pragma unroll
        for (int i = 0; i < 8; i++) { S1 += sm[i]; S2 += sm[8 + i]; }
        float mean = S1 / (float)D_;
        float var  = S2 / (float)D_ - mean * mean;
        sm[16] = mean;
        sm[17] = rsqrtf(var + 1e-5f);
    }
    __syncthreads();
    float mean = sm[16], inv = sm[17];
    const float4* wv = (const float4*)w;
    const float4* bv = (const float4*)b;
    float4* ov = (float4*)(out + (size_t)row * D_);
    #pragma unroll
    for (int u = 0; u < 2; u++) {
        int idx = threadIdx.x * 2 + u;
        float4 v = (u == 0) ? v0 : v1;
        float4 W = wv[idx], B = bv[idx], O;
        O.x = (v.x - mean) * inv * W.x + B.x;
        O.y = (v.y - mean) * inv * W.y + B.y;
        O.z = (v.z - mean) * inv * W.z + B.z;
        O.w = (v.w - mean) * inv * W.w + B.w;
        ov[idx] = O;
    }
}

// ---------------- SGEMM 128x128x8, 256 threads, f32x2 FMA ----------------
// C[M,N] = A[M,K] @ B[K,N] (+ res). All row-major fp32. M,N,K multiples of 128/8.
__global__ __launch_bounds__(256) void sgemm_kernel(const float* __restrict__ A,
                                                    const float* __restrict__ B,
                                                    const float* __restrict__ res,
                                                    float* __restrict__ C,
                                                    int M, int N, int K) {
    __shared__ float As[8][128];
    __shared__ float Bs[8][128];
    const int tid = threadIdx.x;
    const int bm = blockIdx.y * 128;
    const int bn = blockIdx.x * 128;

    const int a_row = tid >> 1;          // 0..127
    const int a_col = (tid & 1) * 4;     // 0 or 4
    const int b_row = tid >> 5;          // 0..7
    const int b_col = (tid & 31) * 4;    // 0..124

    const int tx = tid & 15;             // 0..15
    const int ty = tid >> 4;             // 0..15

    unsigned long long acc[8][4];
    #pragma unroll
    for (int i = 0; i < 8; i++)
        #pragma unroll
        for (int p = 0; p < 4; p++) acc[i][p] = 0ull;

    const float* Ap = A + (size_t)(bm + a_row) * K + a_col;
    const float* Bp = B + (size_t)b_row * N + bn + b_col;

    for (int k0 = 0; k0 < K; k0 += 8) {
        float4 av = *(const float4*)(Ap + k0);
        float4 bv = *(const float4*)(Bp + (size_t)k0 * N);
        __syncthreads();
        As[a_col + 0][a_row] = av.x;
        As[a_col + 1][a_row] = av.y;
        As[a_col + 2][a_row] = av.z;
        As[a_col + 3][a_row] = av.w;
        *(float4*)&Bs[b_row][b_col] = bv;
        __syncthreads();
        #pragma unroll
        for (int k = 0; k < 8; k++) {
            float4 a0 = *(const float4*)&As[k][ty * 4];
            float4 a1 = *(const float4*)&As[k][64 + ty * 4];
            unsigned long long b0 = *(const unsigned long long*)&Bs[k][tx * 4];
            unsigned long long b1 = *(const unsigned long long*)&Bs[k][tx * 4 + 2];
            unsigned long long b2 = *(const unsigned long long*)&Bs[k][64 + tx * 4];
            unsigned long long b3 = *(const unsigned long long*)&Bs[k][64 + tx * 4 + 2];
            float a[8] = {a0.x, a0.y, a0.z, a0.w, a1.x, a1.y, a1.z, a1.w};
            #pragma unroll
            for (int i = 0; i < 8; i++) {
                unsigned long long avp = splat2(a[i]);
                fma2(acc[i][0], avp, b0);
                fma2(acc[i][1], avp, b1);
                fma2(acc[i][2], avp, b2);
                fma2(acc[i][3], avp, b3);
            }
        }
    }

    #pragma unroll
    for (int i = 0; i < 8; i++) {
        int r = bm + ((i < 4) ? (ty * 4 + i) : (64 + ty * 4 + (i - 4)));
        #pragma unroll
        for (int p = 0; p < 4; p++) {
            int c = bn + ((p < 2) ? (tx * 4 + 2 * p) : (64 + tx * 4 + 2 * (p - 2)));
            float2 val = unpack2(acc[i][p]);
            size_t idx = (size_t)r * N + c;
            if (res) { val.x += res[idx]; val.y += res[idx + 1]; }
            *(float2*)&C[idx] = val;
        }
    }
}

// ---------------- RoPE (interleaved pairs), fp64 trig for accuracy ----------------
__global__ void rope_kernel(float* __restrict__ x, int H, int total) {
    int i = blockIdx.x * blockDim.x + threadIdx.x;
    if (i >= total) return;
    int p = i & 31;
    int h = (i >> 5) % H;
    int s = i / (32 * H);
    double freq = pow(10000.0, -(double)p / 32.0);
    double ang = (double)s * freq;
    float c = (float)cos(ang);
    float sn = (float)sin(ang);
    float* base = x + ((size_t)s * H + h) * HD_;
    float xr = base[2 * p], xi = base[2 * p + 1];
    base[2 * p]     = xr * c - xi * sn;
    base[2 * p + 1] = xr * sn + xi * c;
}

// ---------------- Flash attention: block = (head, 32 queries), 256 threads ----------------
// 8 threads per query, each owns dims {lane8 + 8*d}, online softmax over 64-key tiles.
__global__ __launch_bounds__(256) void attn_kernel(const float* __restrict__ Q,
                                                   const float* __restrict__ K,
                                                   const float* __restrict__ V,
                                                   const int* __restrict__ mask,
                                                   float* __restrict__ O) {
    __shared__ float Ks[64][64];
    __shared__ float Vs[64][64];
    __shared__ float bias[64];
    const int h = blockIdx.y;
    const int kvh = h >> 2;            // N_REP = 4
    const int tid = threadIdx.x;
    const int qi = tid >> 3;           // 0..31
    const int lane8 = tid & 7;         // 0..7
    const int qrow = blockIdx.x * 32 + qi;

    float qreg[8];
    const float* qp = Q + (size_t)qrow * D_ + h * HD_;
    #pragma unroll
    for (int d = 0; d < 8; d++) qreg[d] = qp[lane8 + 8 * d] * 0.125f;

    float m = -INFINITY, l = 0.f;
    float o[8] = {0.f, 0.f, 0.f, 0.f, 0.f, 0.f, 0.f, 0.f};

    const int r  = tid >> 2;           // 0..63
    const int c4 = (tid & 3) * 16;     // 0,16,32,48

    for (int kt = 0; kt < S_; kt += 64) {
        const float* kp = K + ((size_t)(kt + r) * NKV_ + kvh) * HD_ + c4;
        const float* vp = V + ((size_t)(kt + r) * NKV_ + kvh) * HD_ + c4;
        __syncthreads();
        #pragma unroll
        for (int u = 0; u < 4; u++) {
            *(float4*)&Ks[r][c4 + u * 4] = *(const float4*)(kp + u * 4);
            *(float4*)&Vs[r][c4 + u * 4] = *(const float4*)(vp + u * 4);
        }
        if (tid < 64) bias[tid] = (mask[kt + tid] == 0) ? -1e30f : 0.f;
        __syncthreads();

        #pragma unroll 2
        for (int j = 0; j < 64; j++) {
            float sc = 0.f;
            #pragma unroll
            for (int d = 0; d < 8; d++) sc += qreg[d] * Ks[j][lane8 + 8 * d];
            sc += __shfl_xor_sync(0xffffffffu, sc, 1);
            sc += __shfl_xor_sync(0xffffffffu, sc, 2);
            sc += __shfl_xor_sync(0xffffffffu, sc, 4);
            sc += bias[j];
            if (sc > m) {
                float f = __expf(m - sc);
                m = sc;
                l = l * f + 1.f;
                #pragma unroll
                for (int d = 0; d < 8; d++) o[d] = o[d] * f + Vs[j][lane8 + 8 * d];
            } else {
                float p = __expf(sc - m);
                l += p;
                #pragma unroll
                for (int d = 0; d < 8; d++) o[d] += p * Vs[j][lane8 + 8 * d];
            }
        }
    }
    float inv = 1.f / l;
    float* op = O + (size_t)qrow * D_ + h * HD_;
    #pragma unroll
    for (int d = 0; d < 8; d++) op[lane8 + 8 * d] = o[d] * inv;
}

// ---------------- SiLU(p1) * p3 -> p1 (in place) ----------------
__global__ void silumul_kernel(float* __restrict__ p1, const float* __restrict__ p3, int n4) {
    int i = blockIdx.x * blockDim.x + threadIdx.x;
    if (i >= n4) return;
    float4 a = ((float4*)p1)[i];
    float4 c = ((const float4*)p3)[i];
    a.x = a.x / (1.f + __expf(-a.x)) * c.x;
    a.y = a.y / (1.f + __expf(-a.y)) * c.y;
    a.z = a.z / (1.f + __expf(-a.z)) * c.z;
    a.w = a.w / (1.f + __expf(-a.w)) * c.w;
    ((float4*)p1)[i] = a;
}

// ---------------- launch ----------------
static void gemm(const float* A, const float* B, const float* res, float* C, int M, int N, int K) {
    dim3 grid(N / 128, M / 128);
    sgemm_kernel<<<grid, 256>>>(A, B, res, C, M, N, K);
}

extern "C" void kernel_launch(void* const* d_in, const int* in_sizes, int n_in,
                              void* d_out, int out_size) {
    const float* x    = (const float*)d_in[0];
    const int*   mask = (const int*)  d_in[1];
    const float* wq   = (const float*)d_in[2];
    const float* wk   = (const float*)d_in[3];
    const float* wv   = (const float*)d_in[4];
    const float* wo   = (const float*)d_in[5];
    const float* w1   = (const float*)d_in[6];
    const float* w2   = (const float*)d_in[7];
    const float* w3   = (const float*)d_in[8];
    const float* ln1w = (const float*)d_in[9];
    const float* ln1b = (const float*)d_in[10];
    const float* ln2w = (const float*)d_in[11];
    const float* ln2b = (const float*)d_in[12];
    float* out = (float*)d_out;

    float *h, *q, *k, *v, *ao, *x1, *h2, *p1, *p3;
    cudaGetSymbolAddress((void**)&h,  g_h);
    cudaGetSymbolAddress((void**)&q,  g_q);
    cudaGetSymbolAddress((void**)&k,  g_k);
    cudaGetSymbolAddress((void**)&v,  g_v);
    cudaGetSymbolAddress((void**)&ao, g_ao);
    cudaGetSymbolAddress((void**)&x1, g_x1);
    cudaGetSymbolAddress((void**)&h2, g_h2);
    cudaGetSymbolAddress((void**)&p1, g_p1);
    cudaGetSymbolAddress((void**)&p3, g_p3);

    // h = LN1(x)
    ln_kernel<<<S_, 256>>>(x, ln1w, ln1b, h);
    // q,k,v projections
    gemm(h, wq, nullptr, q, S_, D_,  D_);
    gemm(h, wk, nullptr, k, S_, KV_, D_);
    gemm(h, wv, nullptr, v, S_, KV_, D_);
    // RoPE
    {
        int tq = S_ * NH_ * 32, tk = S_ * NKV_ * 32;
        rope_kernel<<<(tq + 255) / 256, 256>>>(q, NH_,  tq);
        rope_kernel<<<(tk + 255) / 256, 256>>>(k, NKV_, tk);
    }
    // attention
    attn_kernel<<<dim3(S_ / 32, NH_), 256>>>(q, k, v, mask, ao);
    // x1 = x + ao @ wo
    gemm(ao, wo, x, x1, S_, D_, D_);
    // h2 = LN2(x1)
    ln_kernel<<<S_, 256>>>(x1, ln2w, ln2b, h2);
    // FFN
    gemm(h2, w1, nullptr, p1, S_, HID_, D_);
    gemm(h2, w3, nullptr, p3, S_, HID_, D_);
    silumul_kernel<<<(S_ * HID_ / 4 + 255) / 256, 256>>>(p1, p3, S_ * HID_ / 4);
    // out = x1 + (silu(p1)*p3) @ w2
    gemm(p1, w2, x1, out, S_, D_, HID_);
}

// round 2
// speedup vs baseline: 2.6772x; 2.6772x over previous
#include <cuda_runtime.h>
#include <cuda_bf16.h>
#include <math.h>
#include <stdint.h>

// ---------------- problem constants ----------------
#define S_    2048
#define D_    2048
#define HID_  5632
#define NH_   32
#define NKV_  8
#define HD_   64
#define KV_   (NKV_*HD_)   // 512

// ---------------- scratch (no allocation allowed) ----------------
__device__ float g_h [S_*D_];
__device__ float g_q [S_*D_];
__device__ float g_k [S_*KV_];
__device__ float g_v [S_*KV_];
__device__ float g_ao[S_*D_];
__device__ float g_x1[S_*D_];
__device__ float g_h2[S_*D_];
__device__ float g_p1[S_*HID_];
__device__ float g_p3[S_*HID_];

// ---------------- tf32 helpers ----------------
__device__ __forceinline__ uint32_t to_tf32(float f) {
    uint32_t r;
    asm("cvt.rna.tf32.f32 %0, %1;" : "=r"(r) : "f"(f));
    return r;
}
__device__ __forceinline__ void mma_tf32(float* c, const uint32_t* a, const uint32_t* b) {
    asm volatile(
        "mma.sync.aligned.m16n8k8.row.col.f32.tf32.tf32.f32 "
        "{%0,%1,%2,%3}, {%4,%5,%6,%7}, {%8,%9}, {%0,%1,%2,%3};"
        : "+f"(c[0]), "+f"(c[1]), "+f"(c[2]), "+f"(c[3])
        : "r"(a[0]), "r"(a[1]), "r"(a[2]), "r"(a[3]), "r"(b[0]), "r"(b[1]));
}

// ---------------- TF32 tensor-core GEMM ----------------
// C[M,N] = A[M,K] @ B[K,N] (+res). Row-major fp32 in/out, tf32 mma inside.
// Block tile 128x128x16, 8 warps (2m x 4n), warp tile 64x32 (4x4 m16n8k8 frags).
#define APAD 20   // uints per A smem row (16 + 4) -> conflict-free frag loads
#define BPAD 136  // uints per B smem row (128 + 8) -> conflict-free frag loads

__global__ __launch_bounds__(256) void gemm_tf32_kernel(const float* __restrict__ A,
                                                        const float* __restrict__ B,
                                                        const float* __restrict__ res,
                                                        float* __restrict__ C,
                                                        int M, int N, int K) {
    __shared__ uint32_t Asm[2][128 * APAD];
    __shared__ uint32_t Bsm[2][16 * BPAD];

    const int tid  = threadIdx.x;
    const int lane = tid & 31;
    const int wid  = tid >> 5;
    const int wm   = wid >> 2;   // 0..1
    const int wn   = wid & 3;    // 0..3
    const int bm   = blockIdx.y * 128;
    const int bn   = blockIdx.x * 128;

    // global-load mapping
    const int am  = tid >> 1;            // A row within tile (0..127)
    const int ak  = (tid & 1) * 8;       // A col base (0 or 8)
    const int bkr = tid >> 4;            // B row within tile (0..15)
    const int bn0 = (tid & 15) * 8;      // B col base (0..120)

    const float* Ag = A + (size_t)(bm + am) * K + ak;
    const float* Bg = B + (size_t)bkr * N + bn + bn0;

    float c[4][4][4];
    #pragma unroll
    for (int t = 0; t < 4; t++)
        #pragma unroll
        for (int u = 0; u < 4; u++)
            #pragma unroll
            for (int i = 0; i < 4; i++) c[t][u][i] = 0.f;

    const int NT = K >> 4;
    float4 a0v, a1v, b0v, b1v;

    // prologue: tile 0
    a0v = *(const float4*)(Ag);
    a1v = *(const float4*)(Ag + 4);
    b0v = *(const float4*)(Bg);
    b1v = *(const float4*)(Bg + 4);
    {
        uint32_t* As = Asm[0];
        uint32_t* Bs = Bsm[0];
        uint4 ua = { to_tf32(a0v.x), to_tf32(a0v.y), to_tf32(a0v.z), to_tf32(a0v.w) };
        uint4 ub = { to_tf32(a1v.x), to_tf32(a1v.y), to_tf32(a1v.z), to_tf32(a1v.w) };
        *(uint4*)&As[am * APAD + ak]     = ua;
        *(uint4*)&As[am * APAD + ak + 4] = ub;
        uint4 vb0 = { to_tf32(b0v.x), to_tf32(b0v.y), to_tf32(b0v.z), to_tf32(b0v.w) };
        uint4 vb1 = { to_tf32(b1v.x), to_tf32(b1v.y), to_tf32(b1v.z), to_tf32(b1v.w) };
        *(uint4*)&Bs[bkr * BPAD + bn0]     = vb0;
        *(uint4*)&Bs[bkr * BPAD + bn0 + 4] = vb1;
    }
    __syncthreads();

    const int r  = lane >> 2;
    const int cc = lane & 3;

    for (int kt = 0; kt < NT; kt++) {
        // prefetch next tile to regs
        if (kt + 1 < NT) {
            const float* Agn = Ag + (size_t)(kt + 1) * 16;
            const float* Bgn = Bg + (size_t)(kt + 1) * 16 * N;
            a0v = *(const float4*)(Agn);
            a1v = *(const float4*)(Agn + 4);
            b0v = *(const float4*)(Bgn);
            b1v = *(const float4*)(Bgn + 4);
        }
        // compute current buffer
        {
            const uint32_t* As = Asm[kt & 1];
            const uint32_t* Bs = Bsm[kt & 1];
            #pragma unroll
            for (int s = 0; s < 2; s++) {
                uint32_t af[4][4], bf[4][2];
                #pragma unroll
                for (int t = 0; t < 4; t++) {
                    int row = wm * 64 + t * 16 + r;
                    af[t][0] = As[row * APAD + s * 8 + cc];
                    af[t][1] = As[(row + 8) * APAD + s * 8 + cc];
                    af[t][2] = As[row * APAD + s * 8 + cc + 4];
                    af[t][3] = As[(row + 8) * APAD + s * 8 + cc + 4];
                }
                #pragma unroll
                for (int u = 0; u < 4; u++) {
                    int col = wn * 32 + u * 8 + r;
                    bf[u][0] = Bs[(s * 8 + cc) * BPAD + col];
                    bf[u][1] = Bs[(s * 8 + cc + 4) * BPAD + col];
                }
                #pragma unroll
                for (int t = 0; t < 4; t++)
                    #pragma unroll
                    for (int u = 0; u < 4; u++)
                        mma_tf32(c[t][u], af[t], bf[u]);
            }
        }
        // store next buffer
        if (kt + 1 < NT) {
            uint32_t* As = Asm[(kt + 1) & 1];
            uint32_t* Bs = Bsm[(kt + 1) & 1];
            uint4 ua = { to_tf32(a0v.x), to_tf32(a0v.y), to_tf32(a0v.z), to_tf32(a0v.w) };
            uint4 ub = { to_tf32(a1v.x), to_tf32(a1v.y), to_tf32(a1v.z), to_tf32(a1v.w) };
            *(uint4*)&As[am * APAD + ak]     = ua;
            *(uint4*)&As[am * APAD + ak + 4] = ub;
            uint4 vb0 = { to_tf32(b0v.x), to_tf32(b0v.y), to_tf32(b0v.z), to_tf32(b0v.w) };
            uint4 vb1 = { to_tf32(b1v.x), to_tf32(b1v.y), to_tf32(b1v.z), to_tf32(b1v.w) };
            *(uint4*)&Bs[bkr * BPAD + bn0]     = vb0;
            *(uint4*)&Bs[bkr * BPAD + bn0 + 4] = vb1;
        }
        __syncthreads();
    }

    // epilogue
    #pragma unroll
    for (int t = 0; t < 4; t++) {
        int gr = bm + wm * 64 + t * 16 + r;
        #pragma unroll
        for (int u = 0; u < 4; u++) {
            int gc = bn + wn * 32 + u * 8 + cc * 2;
            size_t i0 = (size_t)gr * N + gc;
            size_t i1 = (size_t)(gr + 8) * N + gc;
            float2 v0 = { c[t][u][0], c[t][u][1] };
            float2 v1 = { c[t][u][2], c[t][u][3] };
            if (res) {
                const float2 r0 = *(const float2*)&res[i0];
                const float2 r1 = *(const float2*)&res[i1];
                v0.x += r0.x; v0.y += r0.y;
                v1.x += r1.x; v1.y += r1.y;
            }
            *(float2*)&C[i0] = v0;
            *(float2*)&C[i1] = v1;
        }
    }
}

// ---------------- LayerNorm: one block per row, 256 threads ----------------
__global__ __launch_bounds__(256) void ln_kernel(const float* __restrict__ x,
                                                 const float* __restrict__ w,
                                                 const float* __restrict__ b,
                                                 float* __restrict__ out) {
    int row = blockIdx.x;
    const float4* xr = (const float4*)(x + (size_t)row * D_);
    float4 v0 = xr[threadIdx.x * 2 + 0];
    float4 v1 = xr[threadIdx.x * 2 + 1];
    float s  = v0.x + v0.y + v0.z + v0.w + v1.x + v1.y + v1.z + v1.w;
    float ss = v0.x*v0.x + v0.y*v0.y + v0.z*v0.z + v0.w*v0.w
             + v1.x*v1.x + v1.y*v1.y + v1.z*v1.z + v1.w*v1.w;
    #pragma unroll
    for (int o = 16; o; o >>= 1) {
        s  += __shfl_xor_sync(0xffffffffu, s,  o);
        ss += __shfl_xor_sync(0xffffffffu, ss, o);
    }
    __shared__ float sm[18];
    int warp = threadIdx.x >> 5, lane = threadIdx.x & 31;
    if (lane == 0) { sm[warp] = s; sm[8 + warp] = ss; }
    __syncthreads();
    if (threadIdx.x == 0) {
        float S1 = 0.f, S2 = 0.f;
        #pragma unroll
        for (int i = 0; i < 8; i++) { S1 += sm[i]; S2 += sm[8 + i]; }
        float mean = S1 / (float)D_;
        float var  = S2 / (float)D_ - mean * mean;
        sm[16] = mean;
        sm[17] = rsqrtf(var + 1e-5f);
    }
    __syncthreads();
    float mean = sm[16], inv = sm[17];
    const float4* wv = (const float4*)w;
    const float4* bv = (const float4*)b;
    float4* ov = (float4*)(out + (size_t)row * D_);
    #pragma unroll
    for (int u = 0; u < 2; u++) {
        int idx = threadIdx.x * 2 + u;
        float4 v = (u == 0) ? v0 : v1;
        float4 W = wv[idx], B = bv[idx], O;
        O.x = (v.x - mean) * inv * W.x + B.x;
        O.y = (v.y - mean) * inv * W.y + B.y;
        O.z = (v.z - mean) * inv * W.z + B.z;
        O.w = (v.w - mean) * inv * W.w + B.w;
        ov[idx] = O;
    }
}

// ---------------- RoPE (interleaved pairs), fp32 ----------------
__global__ void rope_kernel(float* __restrict__ x, int H, int total) {
    int i = blockIdx.x * blockDim.x + threadIdx.x;
    if (i >= total) return;
    int p = i & 31;
    int h = (i >> 5) % H;
    int s = i / (32 * H);
    // freq = 10000^(-p/32) = exp2(-p * log2(10000)/32)
    float freq = exp2f(-(float)p * 0.415241011860920f);
    float ang = (float)s * freq;
    float c, sn;
    sincosf(ang, &sn, &c);
    float* base = x + ((size_t)s * H + h) * HD_;
    float xr = base[2 * p], xi = base[2 * p + 1];
    base[2 * p]     = xr * c - xi * sn;
    base[2 * p + 1] = xr * sn + xi * c;
}

// ---------------- Flash attention: block = (head, 32 queries), 256 threads ----------------
__global__ __launch_bounds__(256) void attn_kernel(const float* __restrict__ Q,
                                                   const float* __restrict__ K,
                                                   const float* __restrict__ V,
                                                   const int* __restrict__ mask,
                                                   float* __restrict__ O) {
    __shared__ float Ks[64][64];
    __shared__ float Vs[64][64];
    __shared__ float bias[64];
    const int h = blockIdx.y;
    const int kvh = h >> 2;            // N_REP = 4
    const int tid = threadIdx.x;
    const int qi = tid >> 3;           // 0..31
    const int lane8 = tid & 7;         // 0..7
    const int qrow = blockIdx.x * 32 + qi;

    float qreg[8];
    const float* qp = Q + (size_t)qrow * D_ + h * HD_;
    #pragma unroll
    for (int d = 0; d < 8; d++) qreg[d] = qp[lane8 + 8 * d] * 0.125f;

    float m = -INFINITY, l = 0.f;
    float o[8] = {0.f, 0.f, 0.f, 0.f, 0.f, 0.f, 0.f, 0.f};

    const int r  = tid >> 2;           // 0..63
    const int c4 = (tid & 3) * 16;     // 0,16,32,48

    for (int kt = 0; kt < S_; kt += 64) {
        const float* kp = K + ((size_t)(kt + r) * NKV_ + kvh) * HD_ + c4;
        const float* vp = V + ((size_t)(kt + r) * NKV_ + kvh) * HD_ + c4;
        __syncthreads();
        #pragma unroll
        for (int u = 0; u < 4; u++) {
            *(float4*)&Ks[r][c4 + u * 4] = *(const float4*)(kp + u * 4);
            *(float4*)&Vs[r][c4 + u * 4] = *(const float4*)(vp + u * 4);
        }
        if (tid < 64) bias[tid] = (mask[kt + tid] == 0) ? -1e30f : 0.f;
        __syncthreads();

        #pragma unroll 2
        for (int j = 0; j < 64; j++) {
            float sc = 0.f;
            #pragma unroll
            for (int d = 0; d < 8; d++) sc += qreg[d] * Ks[j][lane8 + 8 * d];
            sc += __shfl_xor_sync(0xffffffffu, sc, 1);
            sc += __shfl_xor_sync(0xffffffffu, sc, 2);
            sc += __shfl_xor_sync(0xffffffffu, sc, 4);
            sc += bias[j];
            if (sc > m) {
                float f = __expf(m - sc);
                m = sc;
                l = l * f + 1.f;
                #pragma unroll
                for (int d = 0; d < 8; d++) o[d] = o[d] * f + Vs[j][lane8 + 8 * d];
            } else {
                float p = __expf(sc - m);
                l += p;
                #pragma unroll
                for (int d = 0; d < 8; d++) o[d] += p * Vs[j][lane8 + 8 * d];
            }
        }
    }
    float inv = 1.f / l;
    float* op = O + (size_t)qrow * D_ + h * HD_;
    #pragma unroll
    for (int d = 0; d < 8; d++) op[lane8 + 8 * d] = o[d] * inv;
}

// ---------------- SiLU(p1) * p3 -> p1 (in place) ----------------
__global__ void silumul_kernel(float* __restrict__ p1, const float* __restrict__ p3, int n4) {
    int i = blockIdx.x * blockDim.x + threadIdx.x;
    if (i >= n4) return;
    float4 a = ((float4*)p1)[i];
    float4 c = ((const float4*)p3)[i];
    a.x = a.x / (1.f + __expf(-a.x)) * c.x;
    a.y = a.y / (1.f + __expf(-a.y)) * c.y;
    a.z = a.z / (1.f + __expf(-a.z)) * c.z;
    a.w = a.w / (1.f + __expf(-a.w)) * c.w;
    ((float4*)p1)[i] = a;
}

// ---------------- launch ----------------
static void gemm(const float* A, const float* B, const float* res, float* C, int M, int N, int K) {
    dim3 grid(N / 128, M / 128);
    gemm_tf32_kernel<<<grid, 256>>>(A, B, res, C, M, N, K);
}

extern "C" void kernel_launch(void* const* d_in, const int* in_sizes, int n_in,
                              void* d_out, int out_size) {
    const float* x    = (const float*)d_in[0];
    const int*   mask = (const int*)  d_in[1];
    const float* wq   = (const float*)d_in[2];
    const float* wk   = (const float*)d_in[3];
    const float* wv   = (const float*)d_in[4];
    const float* wo   = (const float*)d_in[5];
    const float* w1   = (const float*)d_in[6];
    const float* w2   = (const float*)d_in[7];
    const float* w3   = (const float*)d_in[8];
    const float* ln1w = (const float*)d_in[9];
    const float* ln1b = (const float*)d_in[10];
    const float* ln2w = (const float*)d_in[11];
    const float* ln2b = (const float*)d_in[12];
    float* out = (float*)d_out;

    float *h, *q, *k, *v, *ao, *x1, *h2, *p1, *p3;
    cudaGetSymbolAddress((void**)&h,  g_h);
    cudaGetSymbolAddress((void**)&q,  g_q);
    cudaGetSymbolAddress((void**)&k,  g_k);
    cudaGetSymbolAddress((void**)&v,  g_v);
    cudaGetSymbolAddress((void**)&ao, g_ao);
    cudaGetSymbolAddress((void**)&x1, g_x1);
    cudaGetSymbolAddress((void**)&h2, g_h2);
    cudaGetSymbolAddress((void**)&p1, g_p1);
    cudaGetSymbolAddress((void**)&p3, g_p3);

    // h = LN1(x)
    ln_kernel<<<S_, 256>>>(x, ln1w, ln1b, h);
    // q,k,v projections
    gemm(h, wq, nullptr, q, S_, D_,  D_);
    gemm(h, wk, nullptr, k, S_, KV_, D_);
    gemm(h, wv, nullptr, v, S_, KV_, D_);
    // RoPE
    {
        int tq = S_ * NH_ * 32, tk = S_ * NKV_ * 32;
        rope_kernel<<<(tq + 255) / 256, 256>>>(q, NH_,  tq);
        rope_kernel<<<(tk + 255) / 256, 256>>>(k, NKV_, tk);
    }
    // attention
    attn_kernel<<<dim3(S_ / 32, NH_), 256>>>(q, k, v, mask, ao);
    // x1 = x + ao @ wo
    gemm(ao, wo, x, x1, S_, D_, D_);
    // h2 = LN2(x1)
    ln_kernel<<<S_, 256>>>(x1, ln2w, ln2b, h2);
    // FFN
    gemm(h2, w1, nullptr, p1, S_, HID_, D_);
    gemm(h2, w3, nullptr, p3, S_, HID_, D_);
    silumul_kernel<<<(S_ * HID_ / 4 + 255) / 256, 256>>>(p1, p3, S_ * HID_ / 4);
    // out = x1 + (silu(p1)*p3) @ w2
    gemm(p1, w2, x1, out, S_, D_, HID_);
}